// round 12
// baseline (speedup 1.0000x reference)
#include <cuda_runtime.h>
#include <cuda_fp16.h>
#include <cstdint>

// ---------------------------------------------------------------------------
// out[8192,11008] = x[8192,4096] @ dequant(W)[11008,4096]^T
// W: int8 stored in int32; scales[11008, 32], group=128 along K.
// fp16 scratch prepass + cp.async/ldmatrix/mma.sync.m16n8k16 GEMM.
// Round 12: persistent CTAs. Inner 64-chunk loop is the proven branchless
// R8/R11 structure, unchanged. At each tile boundary the next tile's first
// 3 stages are issued BEFORE the epilogue stores, overlapping the pipeline
// fill (previously cold per CTA) with the output writeback.
// ---------------------------------------------------------------------------
#define MM 8192
#define NN 11008
#define KK 4096

#define TM 128
#define TN 128
#define KC 64                              // 64 halves = 128B rows
#define KTILES (KK / KC)                   // 64
#define STAGES 3
#define A_BYTES (TM * KC * 2)              // 16384
#define B_BYTES (TN * KC * 2)              // 16384
#define STAGE_BYTES (A_BYTES + B_BYTES)    // 32768
#define SMEM_TOTAL (STAGES * STAGE_BYTES)  // 98304
#define NTM (MM / TM)                      // 64
#define NTN (NN / TN)                      // 86
#define NTILES (NTM * NTN)                 // 5504

__device__ __half g_x[(size_t)MM * KK];    // 67 MB
__device__ __half g_w[(size_t)NN * KK];    // 90 MB

// ---------------------------------------------------------------------------
// PTX helpers (baseline PTX, valid on compute_103)
// ---------------------------------------------------------------------------
__device__ __forceinline__ uint32_t smem_u32(const void* p) {
    uint32_t a;
    asm("{ .reg .u64 t; cvta.to.shared.u64 t, %1; cvt.u32.u64 %0, t; }"
        : "=r"(a) : "l"(p));
    return a;
}

__device__ __forceinline__ void cp16(uint32_t dst, const void* src) {
    asm volatile("cp.async.cg.shared.global [%0], [%1], 16;"
                 :: "r"(dst), "l"(src));
}
__device__ __forceinline__ void cp_commit() {
    asm volatile("cp.async.commit_group;" ::: "memory");
}
template <int N>
__device__ __forceinline__ void cp_wait() {
    asm volatile("cp.async.wait_group %0;" :: "n"(N) : "memory");
}

__device__ __forceinline__ void ldsm4(uint32_t* r, uint32_t addr) {
    asm volatile("ldmatrix.sync.aligned.m8n8.x4.shared.b16 {%0,%1,%2,%3}, [%4];"
                 : "=r"(r[0]), "=r"(r[1]), "=r"(r[2]), "=r"(r[3]) : "r"(addr));
}

__device__ __forceinline__ void mma16816(float* d, const uint32_t* a,
                                         const uint32_t* b) {
    asm volatile(
        "mma.sync.aligned.m16n8k16.row.col.f32.f16.f16.f32 "
        "{%0,%1,%2,%3}, {%4,%5,%6,%7}, {%8,%9}, {%0,%1,%2,%3};"
        : "+f"(d[0]), "+f"(d[1]), "+f"(d[2]), "+f"(d[3])
        : "r"(a[0]), "r"(a[1]), "r"(a[2]), "r"(a[3]), "r"(b[0]), "r"(b[1]));
}

__device__ __forceinline__ void stg_cs_v2(float* p, float v0, float v1) {
    asm volatile("st.global.cs.v2.f32 [%0], {%1, %2};"
                 :: "l"(p), "f"(v0), "f"(v1) : "memory");
}

// ---------------------------------------------------------------------------
// Prepass 1: x (fp32) -> g_x (fp16). grid 16384 x 256 exact.
// ---------------------------------------------------------------------------
__global__ void __launch_bounds__(256) prep_x_kernel(const float4* __restrict__ x) {
    size_t i = (size_t)blockIdx.x * 256 + threadIdx.x;
    float4 v0 = x[i * 2], v1 = x[i * 2 + 1];
    __half2 h0 = __floats2half2_rn(v0.x, v0.y);
    __half2 h1 = __floats2half2_rn(v0.z, v0.w);
    __half2 h2 = __floats2half2_rn(v1.x, v1.y);
    __half2 h3 = __floats2half2_rn(v1.z, v1.w);
    uint4 o;
    o.x = *reinterpret_cast<uint32_t*>(&h0);
    o.y = *reinterpret_cast<uint32_t*>(&h1);
    o.z = *reinterpret_cast<uint32_t*>(&h2);
    o.w = *reinterpret_cast<uint32_t*>(&h3);
    reinterpret_cast<uint4*>(g_x)[i] = o;
}

// ---------------------------------------------------------------------------
// Prepass 2: g_w[o,k] = fp16(int8(W) * scales[o, k/128]). grid 22016 x 256.
// ---------------------------------------------------------------------------
__global__ void __launch_bounds__(256) prep_w_kernel(const int4* __restrict__ w,
                                                     const float* __restrict__ sc) {
    size_t i = (size_t)blockIdx.x * 256 + threadIdx.x;   // 8-int chunk
    size_t o = i >> 9;
    int c = (int)(i & 511);
    float s = __ldg(&sc[(o << 5) + (c >> 4)]);
    int4 q0 = w[i * 2], q1 = w[i * 2 + 1];
    __half2 h0 = __floats2half2_rn((float)q0.x * s, (float)q0.y * s);
    __half2 h1 = __floats2half2_rn((float)q0.z * s, (float)q0.w * s);
    __half2 h2 = __floats2half2_rn((float)q1.x * s, (float)q1.y * s);
    __half2 h3 = __floats2half2_rn((float)q1.z * s, (float)q1.w * s);
    uint4 out;
    out.x = *reinterpret_cast<uint32_t*>(&h0);
    out.y = *reinterpret_cast<uint32_t*>(&h1);
    out.z = *reinterpret_cast<uint32_t*>(&h2);
    out.w = *reinterpret_cast<uint32_t*>(&h3);
    reinterpret_cast<uint4*>(g_w)[i] = out;
}

// ---------------------------------------------------------------------------
// GEMM, persistent. CTA 128x128 tiles, 128 threads (2x2 warps of 64x64).
// SMEM rows 128B, XOR-16B swizzle. 3-stage cp.async pipeline, 2 CTAs/SM,
// register double-buffered ldmatrix fragments. Inner loop branchless (R8).
// Tile boundary: sync -> drain -> issue next tile's 3 stages -> epilogue.
// ---------------------------------------------------------------------------
__global__ void __launch_bounds__(128, 2) gemm_kernel(float* __restrict__ out,
                                                      int span) {
    extern __shared__ __align__(1024) char smem[];
    const uint32_t sb = smem_u32(smem);
    const int tid = threadIdx.x;
    const int lid = tid & 31, wid = tid >> 5;
    const int warp_m = wid >> 1, warp_n = wid & 1;      // 2 x 2

    // Per-thread cp.async geometry (tile-independent parts)
    const int rbase = tid >> 3, k4 = tid & 7;
    const uint32_t a_dst0 = sb + rbase * 128 + ((k4 ^ (rbase & 7)) << 4);
    const uint32_t b_dst0 = sb + A_BYTES + rbase * 128 + ((k4 ^ (rbase & 7)) << 4);

    // Tile-dependent source bases (mutated at tile boundaries)
    const __half* a_src0;
    const __half* b_src0;
    int m0, n0;
    auto set_bases = [&](int t) {
        m0 = (t & (NTM - 1)) * TM;          // m fastest (same order as R11 grid)
        n0 = (t >> 6) * TN;
        a_src0 = g_x + (size_t)(m0 + rbase) * KK + k4 * 8;
        b_src0 = g_w + (size_t)(n0 + rbase) * KK + k4 * 8;
    };

    auto issue = [&](int kt) {
        uint32_t so = (uint32_t)(kt % 3) * STAGE_BYTES;
        size_t ko = (size_t)kt * KC;
#pragma unroll
        for (int i = 0; i < 8; i++)                 // A rows rbase+16i
            cp16(a_dst0 + so + i * 2048, a_src0 + ko + (size_t)i * 16 * KK);
#pragma unroll
        for (int i = 0; i < 8; i++)                 // B rows rbase+16i
            cp16(b_dst0 + so + i * 2048, b_src0 + ko + (size_t)i * 16 * KK);
        cp_commit();
    };

    // ---- ldmatrix lane geometry ----
    const int lr = lid & 7;
    const int rowA = warp_m * 64 + lr + ((lid >> 3) & 1) * 8;  // + mi*16
    const int kselA = lid >> 4;                                // + 2*ks
    const int rowB = warp_n * 64 + lr + (lid >> 4) * 8;        // + p*16
    const int kselB = (lid >> 3) & 1;                          // + 2*ks

    uint32_t a[2][4][4], b[2][8][2];
    auto load_frags = [&](uint32_t sA, uint32_t sB, int ks, int buf) {
#pragma unroll
        for (int mi = 0; mi < 4; mi++) {
            uint32_t addr = sA + (uint32_t)(rowA + mi * 16) * 128
                          + ((uint32_t)((2 * ks + kselA) ^ lr) << 4);
            ldsm4(a[buf][mi], addr);
        }
#pragma unroll
        for (int p = 0; p < 4; p++) {
            uint32_t addr = sB + (uint32_t)(rowB + p * 16) * 128
                          + ((uint32_t)((2 * ks + kselB) ^ lr) << 4);
            uint32_t r[4];
            ldsm4(r, addr);
            b[buf][2 * p][0] = r[0];     b[buf][2 * p][1] = r[1];
            b[buf][2 * p + 1][0] = r[2]; b[buf][2 * p + 1][1] = r[3];
        }
    };

    float acc[4][8][4];
    const int g = lid >> 2, tq = lid & 3;

    // ---- first tile prologue ----
    set_bases(blockIdx.x);
    issue(0); issue(1); issue(2);

#pragma unroll 1
    for (int t = blockIdx.x; t < NTILES; t += span) {
        cp_wait<2>();
        __syncthreads();
#pragma unroll
        for (int mi = 0; mi < 4; mi++)
#pragma unroll
            for (int ni = 0; ni < 8; ni++)
#pragma unroll
                for (int q = 0; q < 4; q++) acc[mi][ni][q] = 0.f;
        load_frags(sb, sb + A_BYTES, 0, 0);   // (kt=0, ks=0) -> buf 0

        // ---- inner 64-chunk loop: branchless R8 structure, unchanged ----
#pragma unroll 1
        for (int kt = 0; kt < KTILES; kt++) {
            const uint32_t sA = sb + (uint32_t)(kt % 3) * STAGE_BYTES;
            const uint32_t sB = sA + A_BYTES;
#pragma unroll
            for (int ks = 0; ks < 3; ks++) {
                const int cur = ks & 1, nxt = cur ^ 1;
                load_frags(sA, sB, ks + 1, nxt);
#pragma unroll
                for (int mi = 0; mi < 4; mi++)
#pragma unroll
                    for (int ni = 0; ni < 8; ni++)
                        mma16816(acc[mi][ni], a[cur][mi], b[cur][ni]);
            }
#pragma unroll
            for (int mi = 0; mi < 4; mi++)
#pragma unroll
                for (int ni = 0; ni < 8; ni++)
                    mma16816(acc[mi][ni], a[1][mi], b[1][ni]);

            if (kt + 1 < KTILES) {
                cp_wait<1>();
                __syncthreads();
                issue(kt + 3 < KTILES ? kt + 3 : kt);  // branchless refill
                const uint32_t sAn = sb + (uint32_t)((kt + 1) % 3) * STAGE_BYTES;
                load_frags(sAn, sAn + A_BYTES, 0, 0);
            }
        }

        // ---- tile boundary ----
        const int pm0 = m0, pn0 = n0;
        __syncthreads();     // all warps done with this tile's smem reads
        cp_wait<0>();        // drain leftovers (incl. redundant tail refills)
        if (t + span < NTILES) {
            set_bases(t + span);
            issue(0); issue(1); issue(2);   // next tile fill, under epilogue
        }

        // ---- epilogue (overlaps next tile's loads) ----
#pragma unroll
        for (int mi = 0; mi < 4; mi++) {
            int r0 = pm0 + warp_m * 64 + mi * 16 + g;
#pragma unroll
            for (int ni = 0; ni < 8; ni++) {
                int c = pn0 + warp_n * 64 + ni * 8 + 2 * tq;
                stg_cs_v2(out + (size_t)r0 * NN + c,
                          acc[mi][ni][0], acc[mi][ni][1]);
                stg_cs_v2(out + (size_t)(r0 + 8) * NN + c,
                          acc[mi][ni][2], acc[mi][ni][3]);
            }
        }
    }
}

// ---------------------------------------------------------------------------
// Host
// ---------------------------------------------------------------------------
extern "C" void kernel_launch(void* const* d_in, const int* in_sizes, int n_in,
                              void* d_out, int out_size) {
    const float* x = (const float*)d_in[0];
    const int*   w = (const int*)d_in[1];
    const float* sc = (const float*)d_in[2];
    float* out = (float*)d_out;

    cudaFuncSetAttribute(gemm_kernel,
                         cudaFuncAttributeMaxDynamicSharedMemorySize, SMEM_TOTAL);

    int dev = 0, nsm = 148, nb = 2;
    cudaGetDevice(&dev);
    cudaDeviceGetAttribute(&nsm, cudaDevAttrMultiProcessorCount, dev);
    cudaOccupancyMaxActiveBlocksPerMultiprocessor(&nb, gemm_kernel, 128,
                                                  SMEM_TOTAL);
    if (nb < 1) nb = 1;
    int span = nsm * nb;
    if (span > NTILES) span = NTILES;

    prep_x_kernel<<<16384, 256>>>(reinterpret_cast<const float4*>(x));
    prep_w_kernel<<<22016, 256>>>(reinterpret_cast<const int4*>(w), sc);
    gemm_kernel<<<span, 128, SMEM_TOTAL>>>(out, span);
}

// round 13
// speedup vs baseline: 1.0446x; 1.0446x over previous
#include <cuda_runtime.h>
#include <cuda_fp16.h>
#include <cstdint>

// ---------------------------------------------------------------------------
// out[8192,11008] = x[8192,4096] @ dequant(W)[11008,4096]^T
// W: int8 stored in int32; scales[11008, 32], group=128 along K.
// fp16 scratch prepass + cp.async/ldmatrix/mma.sync.m16n8k16 GEMM.
// Round 13: R11 GEMM verbatim (branchless hot loop, 2 CTAs/SM, double-
// buffered fragments — the reproduced 1521us structure) + fused single
// prepass launch (measured -6us in the R9/R10 A/B pair).
// ---------------------------------------------------------------------------
#define MM 8192
#define NN 11008
#define KK 4096

#define TM 128
#define TN 128
#define KC 64                              // 64 halves = 128B rows
#define KTILES (KK / KC)                   // 64
#define STAGES 3
#define A_BYTES (TM * KC * 2)              // 16384
#define B_BYTES (TN * KC * 2)              // 16384
#define STAGE_BYTES (A_BYTES + B_BYTES)    // 32768
#define SMEM_TOTAL (STAGES * STAGE_BYTES)  // 98304

#define XBLOCKS 16384                      // prep: x part
#define WBLOCKS 22016                      // prep: w part

__device__ __half g_x[(size_t)MM * KK];    // 67 MB
__device__ __half g_w[(size_t)NN * KK];    // 90 MB

// ---------------------------------------------------------------------------
// PTX helpers (baseline PTX, valid on compute_103)
// ---------------------------------------------------------------------------
__device__ __forceinline__ uint32_t smem_u32(const void* p) {
    uint32_t a;
    asm("{ .reg .u64 t; cvta.to.shared.u64 t, %1; cvt.u32.u64 %0, t; }"
        : "=r"(a) : "l"(p));
    return a;
}

__device__ __forceinline__ void cp16(uint32_t dst, const void* src) {
    asm volatile("cp.async.cg.shared.global [%0], [%1], 16;"
                 :: "r"(dst), "l"(src));
}
__device__ __forceinline__ void cp_commit() {
    asm volatile("cp.async.commit_group;" ::: "memory");
}
template <int N>
__device__ __forceinline__ void cp_wait() {
    asm volatile("cp.async.wait_group %0;" :: "n"(N) : "memory");
}

__device__ __forceinline__ void ldsm4(uint32_t* r, uint32_t addr) {
    asm volatile("ldmatrix.sync.aligned.m8n8.x4.shared.b16 {%0,%1,%2,%3}, [%4];"
                 : "=r"(r[0]), "=r"(r[1]), "=r"(r[2]), "=r"(r[3]) : "r"(addr));
}

__device__ __forceinline__ void mma16816(float* d, const uint32_t* a,
                                         const uint32_t* b) {
    asm volatile(
        "mma.sync.aligned.m16n8k16.row.col.f32.f16.f16.f32 "
        "{%0,%1,%2,%3}, {%4,%5,%6,%7}, {%8,%9}, {%0,%1,%2,%3};"
        : "+f"(d[0]), "+f"(d[1]), "+f"(d[2]), "+f"(d[3])
        : "r"(a[0]), "r"(a[1]), "r"(a[2]), "r"(a[3]), "r"(b[0]), "r"(b[1]));
}

__device__ __forceinline__ void stg_cs_v2(float* p, float v0, float v1) {
    asm volatile("st.global.cs.v2.f32 [%0], {%1, %2};"
                 :: "l"(p), "f"(v0), "f"(v1) : "memory");
}

// ---------------------------------------------------------------------------
// Fused prepass: blocks [0, XBLOCKS) convert x -> g_x (fp16);
// blocks [XBLOCKS, XBLOCKS+WBLOCKS) dequantize W -> g_w (fp16).
// ---------------------------------------------------------------------------
__global__ void __launch_bounds__(256) prep_kernel(const float4* __restrict__ x,
                                                   const int4* __restrict__ w,
                                                   const float* __restrict__ sc) {
    int b = blockIdx.x;
    if (b < XBLOCKS) {
        size_t i = (size_t)b * 256 + threadIdx.x;         // 8-float chunk
        float4 v0 = x[i * 2], v1 = x[i * 2 + 1];
        __half2 h0 = __floats2half2_rn(v0.x, v0.y);
        __half2 h1 = __floats2half2_rn(v0.z, v0.w);
        __half2 h2 = __floats2half2_rn(v1.x, v1.y);
        __half2 h3 = __floats2half2_rn(v1.z, v1.w);
        uint4 o;
        o.x = *reinterpret_cast<uint32_t*>(&h0);
        o.y = *reinterpret_cast<uint32_t*>(&h1);
        o.z = *reinterpret_cast<uint32_t*>(&h2);
        o.w = *reinterpret_cast<uint32_t*>(&h3);
        reinterpret_cast<uint4*>(g_x)[i] = o;
    } else {
        size_t i = (size_t)(b - XBLOCKS) * 256 + threadIdx.x;  // 8-int chunk
        size_t o = i >> 9;
        int c = (int)(i & 511);
        float s = __ldg(&sc[(o << 5) + (c >> 4)]);
        int4 q0 = w[i * 2], q1 = w[i * 2 + 1];
        __half2 h0 = __floats2half2_rn((float)q0.x * s, (float)q0.y * s);
        __half2 h1 = __floats2half2_rn((float)q0.z * s, (float)q0.w * s);
        __half2 h2 = __floats2half2_rn((float)q1.x * s, (float)q1.y * s);
        __half2 h3 = __floats2half2_rn((float)q1.z * s, (float)q1.w * s);
        uint4 ov;
        ov.x = *reinterpret_cast<uint32_t*>(&h0);
        ov.y = *reinterpret_cast<uint32_t*>(&h1);
        ov.z = *reinterpret_cast<uint32_t*>(&h2);
        ov.w = *reinterpret_cast<uint32_t*>(&h3);
        reinterpret_cast<uint4*>(g_w)[i] = ov;
    }
}

// ---------------------------------------------------------------------------
// GEMM. CTA 128x128, 128 threads (4 warps as 2x2 grid of 64x64 warp tiles).
// SMEM rows 128B, XOR-16B swizzle. 3-stage cp.async pipeline, 2 CTAs/SM,
// register double-buffered ldmatrix fragments. One barrier per chunk; all
// cross-thread SMEM consumption ordered by wait_group -> barrier.
// Hot loop is BRANCHLESS (R8/R11 structure, reproduced at 1521us twice).
// ---------------------------------------------------------------------------
__global__ void __launch_bounds__(128, 2) gemm_kernel(float* __restrict__ out) {
    extern __shared__ __align__(1024) char smem[];
    const uint32_t sb = smem_u32(smem);
    const int tid = threadIdx.x;
    const int lid = tid & 31, wid = tid >> 5;
    const int warp_m = wid >> 1, warp_n = wid & 1;      // 2 x 2
    const int m0 = blockIdx.x * TM, n0 = blockIdx.y * TN;

    // ---- cp.async bases: 128 thr = 16 rows x 8 chunks; 8 iters of +16 rows.
    // Swizzle phase (k4 ^ (row&7)) invariant under row += 16.
    const int rbase = tid >> 3, k4 = tid & 7;
    const __half* a_src0 = g_x + (size_t)(m0 + rbase) * KK + k4 * 8;
    const __half* b_src0 = g_w + (size_t)(n0 + rbase) * KK + k4 * 8;
    const uint32_t a_dst0 = sb + rbase * 128 + ((k4 ^ (rbase & 7)) << 4);
    const uint32_t b_dst0 = sb + A_BYTES + rbase * 128 + ((k4 ^ (rbase & 7)) << 4);

    auto issue = [&](int kt) {
        uint32_t so = (uint32_t)(kt % 3) * STAGE_BYTES;
        size_t ko = (size_t)kt * KC;
#pragma unroll
        for (int i = 0; i < 8; i++)                 // A rows rbase+16i
            cp16(a_dst0 + so + i * 2048, a_src0 + ko + (size_t)i * 16 * KK);
#pragma unroll
        for (int i = 0; i < 8; i++)                 // B rows rbase+16i
            cp16(b_dst0 + so + i * 2048, b_src0 + ko + (size_t)i * 16 * KK);
        cp_commit();
    };

    // ---- ldmatrix lane geometry ----
    const int lr = lid & 7;
    const int rowA = warp_m * 64 + lr + ((lid >> 3) & 1) * 8;  // + mi*16
    const int kselA = lid >> 4;                                // + 2*ks
    const int rowB = warp_n * 64 + lr + (lid >> 4) * 8;        // + p*16
    const int kselB = (lid >> 3) & 1;                          // + 2*ks

    uint32_t a[2][4][4], b[2][8][2];
    auto load_frags = [&](uint32_t sA, uint32_t sB, int ks, int buf) {
#pragma unroll
        for (int mi = 0; mi < 4; mi++) {
            uint32_t addr = sA + (uint32_t)(rowA + mi * 16) * 128
                          + ((uint32_t)((2 * ks + kselA) ^ lr) << 4);
            ldsm4(a[buf][mi], addr);
        }
#pragma unroll
        for (int p = 0; p < 4; p++) {
            uint32_t addr = sB + (uint32_t)(rowB + p * 16) * 128
                          + ((uint32_t)((2 * ks + kselB) ^ lr) << 4);
            uint32_t r[4];
            ldsm4(r, addr);
            b[buf][2 * p][0] = r[0];     b[buf][2 * p][1] = r[1];
            b[buf][2 * p + 1][0] = r[2]; b[buf][2 * p + 1][1] = r[3];
        }
    };

    float acc[4][8][4];
#pragma unroll
    for (int mi = 0; mi < 4; mi++)
#pragma unroll
        for (int ni = 0; ni < 8; ni++)
#pragma unroll
            for (int q = 0; q < 4; q++) acc[mi][ni][q] = 0.f;

    // ---- prologue: chunk 0 resident AND visible (wait -> barrier) ----
    issue(0); issue(1); issue(2);
    cp_wait<2>();
    __syncthreads();
    load_frags(sb, sb + A_BYTES, 0, 0);   // (kt=0, ks=0) -> buf 0

#pragma unroll 1
    for (int kt = 0; kt < KTILES; kt++) {
        const uint32_t sA = sb + (uint32_t)(kt % 3) * STAGE_BYTES;
        const uint32_t sB = sA + A_BYTES;
        // ks = 0..2: prefetch ks+1 from the (barrier-protected) current chunk
#pragma unroll
        for (int ks = 0; ks < 3; ks++) {
            const int cur = ks & 1, nxt = cur ^ 1;
            load_frags(sA, sB, ks + 1, nxt);
#pragma unroll
            for (int mi = 0; mi < 4; mi++)
#pragma unroll
                for (int ni = 0; ni < 8; ni++)
                    mma16816(acc[mi][ni], a[cur][mi], b[cur][ni]);
        }
        // ks = 3: compute only (buf 1)
#pragma unroll
        for (int mi = 0; mi < 4; mi++)
#pragma unroll
            for (int ni = 0; ni < 8; ni++)
                mma16816(acc[mi][ni], a[1][mi], b[1][ni]);

        if (kt + 1 < KTILES) {
            cp_wait<1>();        // own groups: chunk kt+1 landed
            __syncthreads();     // everyone's chunk kt+1 writes visible;
                                 // stage kt%3 fully consumed by all warps
            issue(kt + 3 < KTILES ? kt + 3 : kt);  // branchless refill
            const uint32_t sAn = sb + (uint32_t)((kt + 1) % 3) * STAGE_BYTES;
            load_frags(sAn, sAn + A_BYTES, 0, 0);  // (kt+1, ks=0) -> buf 0
        }
    }

    // ---- epilogue: streaming fp32 stores (evict-first; output never re-read)
    const int g = lid >> 2, t = lid & 3;
#pragma unroll
    for (int mi = 0; mi < 4; mi++) {
        int r0 = m0 + warp_m * 64 + mi * 16 + g;
#pragma unroll
        for (int ni = 0; ni < 8; ni++) {
            int c = n0 + warp_n * 64 + ni * 8 + 2 * t;
            stg_cs_v2(out + (size_t)r0 * NN + c,
                      acc[mi][ni][0], acc[mi][ni][1]);
            stg_cs_v2(out + (size_t)(r0 + 8) * NN + c,
                      acc[mi][ni][2], acc[mi][ni][3]);
        }
    }
}

// ---------------------------------------------------------------------------
// Host
// ---------------------------------------------------------------------------
extern "C" void kernel_launch(void* const* d_in, const int* in_sizes, int n_in,
                              void* d_out, int out_size) {
    const float* x = (const float*)d_in[0];
    const int*   w = (const int*)d_in[1];
    const float* sc = (const float*)d_in[2];
    float* out = (float*)d_out;

    cudaFuncSetAttribute(gemm_kernel,
                         cudaFuncAttributeMaxDynamicSharedMemorySize, SMEM_TOTAL);

    prep_kernel<<<XBLOCKS + WBLOCKS, 256>>>(reinterpret_cast<const float4*>(x),
                                            reinterpret_cast<const int4*>(w), sc);
    gemm_kernel<<<dim3(MM / TM, NN / TN), 128, SMEM_TOTAL>>>(out);
}

// round 14
// speedup vs baseline: 1.0659x; 1.0204x over previous
#include <cuda_runtime.h>
#include <cuda_fp16.h>
#include <cstdint>

// ---------------------------------------------------------------------------
// out[8192,11008] = x[8192,4096] @ dequant(W)[11008,4096]^T
// W: int8 stored in int32; scales[11008, 32], group=128 along K.
// fp16 scratch prepass + cp.async/ldmatrix/mma.sync.m16n8k16 GEMM.
// Round 14: R13 (fused prep + branchless 1519.7us GEMM) with one micro-
// reorder at the chunk boundary: the dependent load_frags(kt+1, ks=0) is
// issued BEFORE the non-dependent cp.async refill batch, shaving the
// ldmatrix latency exposure after each barrier.
// ---------------------------------------------------------------------------
#define MM 8192
#define NN 11008
#define KK 4096

#define TM 128
#define TN 128
#define KC 64                              // 64 halves = 128B rows
#define KTILES (KK / KC)                   // 64
#define STAGES 3
#define A_BYTES (TM * KC * 2)              // 16384
#define B_BYTES (TN * KC * 2)              // 16384
#define STAGE_BYTES (A_BYTES + B_BYTES)    // 32768
#define SMEM_TOTAL (STAGES * STAGE_BYTES)  // 98304

#define XBLOCKS 16384                      // prep: x part
#define WBLOCKS 22016                      // prep: w part

__device__ __half g_x[(size_t)MM * KK];    // 67 MB
__device__ __half g_w[(size_t)NN * KK];    // 90 MB

// ---------------------------------------------------------------------------
// PTX helpers (baseline PTX, valid on compute_103)
// ---------------------------------------------------------------------------
__device__ __forceinline__ uint32_t smem_u32(const void* p) {
    uint32_t a;
    asm("{ .reg .u64 t; cvta.to.shared.u64 t, %1; cvt.u32.u64 %0, t; }"
        : "=r"(a) : "l"(p));
    return a;
}

__device__ __forceinline__ void cp16(uint32_t dst, const void* src) {
    asm volatile("cp.async.cg.shared.global [%0], [%1], 16;"
                 :: "r"(dst), "l"(src));
}
__device__ __forceinline__ void cp_commit() {
    asm volatile("cp.async.commit_group;" ::: "memory");
}
template <int N>
__device__ __forceinline__ void cp_wait() {
    asm volatile("cp.async.wait_group %0;" :: "n"(N) : "memory");
}

__device__ __forceinline__ void ldsm4(uint32_t* r, uint32_t addr) {
    asm volatile("ldmatrix.sync.aligned.m8n8.x4.shared.b16 {%0,%1,%2,%3}, [%4];"
                 : "=r"(r[0]), "=r"(r[1]), "=r"(r[2]), "=r"(r[3]) : "r"(addr));
}

__device__ __forceinline__ void mma16816(float* d, const uint32_t* a,
                                         const uint32_t* b) {
    asm volatile(
        "mma.sync.aligned.m16n8k16.row.col.f32.f16.f16.f32 "
        "{%0,%1,%2,%3}, {%4,%5,%6,%7}, {%8,%9}, {%0,%1,%2,%3};"
        : "+f"(d[0]), "+f"(d[1]), "+f"(d[2]), "+f"(d[3])
        : "r"(a[0]), "r"(a[1]), "r"(a[2]), "r"(a[3]), "r"(b[0]), "r"(b[1]));
}

__device__ __forceinline__ void stg_cs_v2(float* p, float v0, float v1) {
    asm volatile("st.global.cs.v2.f32 [%0], {%1, %2};"
                 :: "l"(p), "f"(v0), "f"(v1) : "memory");
}

// ---------------------------------------------------------------------------
// Fused prepass: blocks [0, XBLOCKS) convert x -> g_x (fp16);
// blocks [XBLOCKS, XBLOCKS+WBLOCKS) dequantize W -> g_w (fp16).
// ---------------------------------------------------------------------------
__global__ void __launch_bounds__(256) prep_kernel(const float4* __restrict__ x,
                                                   const int4* __restrict__ w,
                                                   const float* __restrict__ sc) {
    int b = blockIdx.x;
    if (b < XBLOCKS) {
        size_t i = (size_t)b * 256 + threadIdx.x;         // 8-float chunk
        float4 v0 = x[i * 2], v1 = x[i * 2 + 1];
        __half2 h0 = __floats2half2_rn(v0.x, v0.y);
        __half2 h1 = __floats2half2_rn(v0.z, v0.w);
        __half2 h2 = __floats2half2_rn(v1.x, v1.y);
        __half2 h3 = __floats2half2_rn(v1.z, v1.w);
        uint4 o;
        o.x = *reinterpret_cast<uint32_t*>(&h0);
        o.y = *reinterpret_cast<uint32_t*>(&h1);
        o.z = *reinterpret_cast<uint32_t*>(&h2);
        o.w = *reinterpret_cast<uint32_t*>(&h3);
        reinterpret_cast<uint4*>(g_x)[i] = o;
    } else {
        size_t i = (size_t)(b - XBLOCKS) * 256 + threadIdx.x;  // 8-int chunk
        size_t o = i >> 9;
        int c = (int)(i & 511);
        float s = __ldg(&sc[(o << 5) + (c >> 4)]);
        int4 q0 = w[i * 2], q1 = w[i * 2 + 1];
        __half2 h0 = __floats2half2_rn((float)q0.x * s, (float)q0.y * s);
        __half2 h1 = __floats2half2_rn((float)q0.z * s, (float)q0.w * s);
        __half2 h2 = __floats2half2_rn((float)q1.x * s, (float)q1.y * s);
        __half2 h3 = __floats2half2_rn((float)q1.z * s, (float)q1.w * s);
        uint4 ov;
        ov.x = *reinterpret_cast<uint32_t*>(&h0);
        ov.y = *reinterpret_cast<uint32_t*>(&h1);
        ov.z = *reinterpret_cast<uint32_t*>(&h2);
        ov.w = *reinterpret_cast<uint32_t*>(&h3);
        reinterpret_cast<uint4*>(g_w)[i] = ov;
    }
}

// ---------------------------------------------------------------------------
// GEMM. CTA 128x128, 128 threads (4 warps as 2x2 grid of 64x64 warp tiles).
// SMEM rows 128B, XOR-16B swizzle. 3-stage cp.async pipeline, 2 CTAs/SM,
// register double-buffered ldmatrix fragments. One barrier per chunk; all
// cross-thread SMEM consumption ordered by wait_group -> barrier.
// Hot loop is BRANCHLESS; boundary order: sync -> dependent LDS -> refill.
// ---------------------------------------------------------------------------
__global__ void __launch_bounds__(128, 2) gemm_kernel(float* __restrict__ out) {
    extern __shared__ __align__(1024) char smem[];
    const uint32_t sb = smem_u32(smem);
    const int tid = threadIdx.x;
    const int lid = tid & 31, wid = tid >> 5;
    const int warp_m = wid >> 1, warp_n = wid & 1;      // 2 x 2
    const int m0 = blockIdx.x * TM, n0 = blockIdx.y * TN;

    // ---- cp.async bases: 128 thr = 16 rows x 8 chunks; 8 iters of +16 rows.
    // Swizzle phase (k4 ^ (row&7)) invariant under row += 16.
    const int rbase = tid >> 3, k4 = tid & 7;
    const __half* a_src0 = g_x + (size_t)(m0 + rbase) * KK + k4 * 8;
    const __half* b_src0 = g_w + (size_t)(n0 + rbase) * KK + k4 * 8;
    const uint32_t a_dst0 = sb + rbase * 128 + ((k4 ^ (rbase & 7)) << 4);
    const uint32_t b_dst0 = sb + A_BYTES + rbase * 128 + ((k4 ^ (rbase & 7)) << 4);

    auto issue = [&](int kt) {
        uint32_t so = (uint32_t)(kt % 3) * STAGE_BYTES;
        size_t ko = (size_t)kt * KC;
#pragma unroll
        for (int i = 0; i < 8; i++)                 // A rows rbase+16i
            cp16(a_dst0 + so + i * 2048, a_src0 + ko + (size_t)i * 16 * KK);
#pragma unroll
        for (int i = 0; i < 8; i++)                 // B rows rbase+16i
            cp16(b_dst0 + so + i * 2048, b_src0 + ko + (size_t)i * 16 * KK);
        cp_commit();
    };

    // ---- ldmatrix lane geometry ----
    const int lr = lid & 7;
    const int rowA = warp_m * 64 + lr + ((lid >> 3) & 1) * 8;  // + mi*16
    const int kselA = lid >> 4;                                // + 2*ks
    const int rowB = warp_n * 64 + lr + (lid >> 4) * 8;        // + p*16
    const int kselB = (lid >> 3) & 1;                          // + 2*ks

    uint32_t a[2][4][4], b[2][8][2];
    auto load_frags = [&](uint32_t sA, uint32_t sB, int ks, int buf) {
#pragma unroll
        for (int mi = 0; mi < 4; mi++) {
            uint32_t addr = sA + (uint32_t)(rowA + mi * 16) * 128
                          + ((uint32_t)((2 * ks + kselA) ^ lr) << 4);
            ldsm4(a[buf][mi], addr);
        }
#pragma unroll
        for (int p = 0; p < 4; p++) {
            uint32_t addr = sB + (uint32_t)(rowB + p * 16) * 128
                          + ((uint32_t)((2 * ks + kselB) ^ lr) << 4);
            uint32_t r[4];
            ldsm4(r, addr);
            b[buf][2 * p][0] = r[0];     b[buf][2 * p][1] = r[1];
            b[buf][2 * p + 1][0] = r[2]; b[buf][2 * p + 1][1] = r[3];
        }
    };

    float acc[4][8][4];
#pragma unroll
    for (int mi = 0; mi < 4; mi++)
#pragma unroll
        for (int ni = 0; ni < 8; ni++)
#pragma unroll
            for (int q = 0; q < 4; q++) acc[mi][ni][q] = 0.f;

    // ---- prologue: chunk 0 resident AND visible (wait -> barrier) ----
    issue(0); issue(1); issue(2);
    cp_wait<2>();
    __syncthreads();
    load_frags(sb, sb + A_BYTES, 0, 0);   // (kt=0, ks=0) -> buf 0

#pragma unroll 1
    for (int kt = 0; kt < KTILES; kt++) {
        const uint32_t sA = sb + (uint32_t)(kt % 3) * STAGE_BYTES;
        const uint32_t sB = sA + A_BYTES;
        const uint32_t sAn = sb + (uint32_t)((kt + 1) % 3) * STAGE_BYTES;
        // ks = 0..2: prefetch ks+1 from the (barrier-protected) current chunk
#pragma unroll
        for (int ks = 0; ks < 3; ks++) {
            const int cur = ks & 1, nxt = cur ^ 1;
            load_frags(sA, sB, ks + 1, nxt);
#pragma unroll
            for (int mi = 0; mi < 4; mi++)
#pragma unroll
                for (int ni = 0; ni < 8; ni++)
                    mma16816(acc[mi][ni], a[cur][mi], b[cur][ni]);
        }
        // ks = 3: compute only (buf 1)
#pragma unroll
        for (int mi = 0; mi < 4; mi++)
#pragma unroll
            for (int ni = 0; ni < 8; ni++)
                mma16816(acc[mi][ni], a[1][mi], b[1][ni]);

        if (kt + 1 < KTILES) {
            cp_wait<1>();        // own groups: chunk kt+1 landed
            __syncthreads();     // everyone's chunk kt+1 writes visible;
                                 // stage kt%3 fully consumed by all warps
            load_frags(sAn, sAn + A_BYTES, 0, 0);  // dependent LDS first
            issue(kt + 3 < KTILES ? kt + 3 : kt);  // branchless refill after
        }
    }

    // ---- epilogue: streaming fp32 stores (evict-first; output never re-read)
    const int g = lid >> 2, t = lid & 3;
#pragma unroll
    for (int mi = 0; mi < 4; mi++) {
        int r0 = m0 + warp_m * 64 + mi * 16 + g;
#pragma unroll
        for (int ni = 0; ni < 8; ni++) {
            int c = n0 + warp_n * 64 + ni * 8 + 2 * t;
            stg_cs_v2(out + (size_t)r0 * NN + c,
                      acc[mi][ni][0], acc[mi][ni][1]);
            stg_cs_v2(out + (size_t)(r0 + 8) * NN + c,
                      acc[mi][ni][2], acc[mi][ni][3]);
        }
    }
}

// ---------------------------------------------------------------------------
// Host
// ---------------------------------------------------------------------------
extern "C" void kernel_launch(void* const* d_in, const int* in_sizes, int n_in,
                              void* d_out, int out_size) {
    const float* x = (const float*)d_in[0];
    const int*   w = (const int*)d_in[1];
    const float* sc = (const float*)d_in[2];
    float* out = (float*)d_out;

    cudaFuncSetAttribute(gemm_kernel,
                         cudaFuncAttributeMaxDynamicSharedMemorySize, SMEM_TOTAL);

    prep_kernel<<<XBLOCKS + WBLOCKS, 256>>>(reinterpret_cast<const float4*>(x),
                                            reinterpret_cast<const int4*>(w), sc);
    gemm_kernel<<<dim3(MM / TM, NN / TN), 128, SMEM_TOTAL>>>(out);
}

// round 15
// speedup vs baseline: 1.0810x; 1.0142x over previous
#include <cuda_runtime.h>
#include <cuda_fp16.h>
#include <cstdint>

// ---------------------------------------------------------------------------
// out[8192,11008] = x[8192,4096] @ dequant(W)[11008,4096]^T
// W: int8 stored in int32; scales[11008, 32], group=128 along K.
// fp16 scratch prepass + cp.async/ldmatrix/mma.sync.m16n8k16 GEMM.
// Round 15: R14 + one reorder: the ks=3 MMA block (register-only, no SMEM
// dependency) is moved AFTER the chunk-boundary sequence, so the barrier
// skew + next-chunk ldmatrix latency + cp.async refill batch all hide
// under ~250 cycles of HMMA work instead of being serially exposed.
// ---------------------------------------------------------------------------
#define MM 8192
#define NN 11008
#define KK 4096

#define TM 128
#define TN 128
#define KC 64                              // 64 halves = 128B rows
#define KTILES (KK / KC)                   // 64
#define STAGES 3
#define A_BYTES (TM * KC * 2)              // 16384
#define B_BYTES (TN * KC * 2)              // 16384
#define STAGE_BYTES (A_BYTES + B_BYTES)    // 32768
#define SMEM_TOTAL (STAGES * STAGE_BYTES)  // 98304

#define XBLOCKS 16384                      // prep: x part
#define WBLOCKS 22016                      // prep: w part

__device__ __half g_x[(size_t)MM * KK];    // 67 MB
__device__ __half g_w[(size_t)NN * KK];    // 90 MB

// ---------------------------------------------------------------------------
// PTX helpers (baseline PTX, valid on compute_103)
// ---------------------------------------------------------------------------
__device__ __forceinline__ uint32_t smem_u32(const void* p) {
    uint32_t a;
    asm("{ .reg .u64 t; cvta.to.shared.u64 t, %1; cvt.u32.u64 %0, t; }"
        : "=r"(a) : "l"(p));
    return a;
}

__device__ __forceinline__ void cp16(uint32_t dst, const void* src) {
    asm volatile("cp.async.cg.shared.global [%0], [%1], 16;"
                 :: "r"(dst), "l"(src));
}
__device__ __forceinline__ void cp_commit() {
    asm volatile("cp.async.commit_group;" ::: "memory");
}
template <int N>
__device__ __forceinline__ void cp_wait() {
    asm volatile("cp.async.wait_group %0;" :: "n"(N) : "memory");
}

__device__ __forceinline__ void ldsm4(uint32_t* r, uint32_t addr) {
    asm volatile("ldmatrix.sync.aligned.m8n8.x4.shared.b16 {%0,%1,%2,%3}, [%4];"
                 : "=r"(r[0]), "=r"(r[1]), "=r"(r[2]), "=r"(r[3]) : "r"(addr));
}

__device__ __forceinline__ void mma16816(float* d, const uint32_t* a,
                                         const uint32_t* b) {
    asm volatile(
        "mma.sync.aligned.m16n8k16.row.col.f32.f16.f16.f32 "
        "{%0,%1,%2,%3}, {%4,%5,%6,%7}, {%8,%9}, {%0,%1,%2,%3};"
        : "+f"(d[0]), "+f"(d[1]), "+f"(d[2]), "+f"(d[3])
        : "r"(a[0]), "r"(a[1]), "r"(a[2]), "r"(a[3]), "r"(b[0]), "r"(b[1]));
}

__device__ __forceinline__ void stg_cs_v2(float* p, float v0, float v1) {
    asm volatile("st.global.cs.v2.f32 [%0], {%1, %2};"
                 :: "l"(p), "f"(v0), "f"(v1) : "memory");
}

// ---------------------------------------------------------------------------
// Fused prepass: blocks [0, XBLOCKS) convert x -> g_x (fp16);
// blocks [XBLOCKS, XBLOCKS+WBLOCKS) dequantize W -> g_w (fp16).
// ---------------------------------------------------------------------------
__global__ void __launch_bounds__(256) prep_kernel(const float4* __restrict__ x,
                                                   const int4* __restrict__ w,
                                                   const float* __restrict__ sc) {
    int b = blockIdx.x;
    if (b < XBLOCKS) {
        size_t i = (size_t)b * 256 + threadIdx.x;         // 8-float chunk
        float4 v0 = x[i * 2], v1 = x[i * 2 + 1];
        __half2 h0 = __floats2half2_rn(v0.x, v0.y);
        __half2 h1 = __floats2half2_rn(v0.z, v0.w);
        __half2 h2 = __floats2half2_rn(v1.x, v1.y);
        __half2 h3 = __floats2half2_rn(v1.z, v1.w);
        uint4 o;
        o.x = *reinterpret_cast<uint32_t*>(&h0);
        o.y = *reinterpret_cast<uint32_t*>(&h1);
        o.z = *reinterpret_cast<uint32_t*>(&h2);
        o.w = *reinterpret_cast<uint32_t*>(&h3);
        reinterpret_cast<uint4*>(g_x)[i] = o;
    } else {
        size_t i = (size_t)(b - XBLOCKS) * 256 + threadIdx.x;  // 8-int chunk
        size_t o = i >> 9;
        int c = (int)(i & 511);
        float s = __ldg(&sc[(o << 5) + (c >> 4)]);
        int4 q0 = w[i * 2], q1 = w[i * 2 + 1];
        __half2 h0 = __floats2half2_rn((float)q0.x * s, (float)q0.y * s);
        __half2 h1 = __floats2half2_rn((float)q0.z * s, (float)q0.w * s);
        __half2 h2 = __floats2half2_rn((float)q1.x * s, (float)q1.y * s);
        __half2 h3 = __floats2half2_rn((float)q1.z * s, (float)q1.w * s);
        uint4 ov;
        ov.x = *reinterpret_cast<uint32_t*>(&h0);
        ov.y = *reinterpret_cast<uint32_t*>(&h1);
        ov.z = *reinterpret_cast<uint32_t*>(&h2);
        ov.w = *reinterpret_cast<uint32_t*>(&h3);
        reinterpret_cast<uint4*>(g_w)[i] = ov;
    }
}

// ---------------------------------------------------------------------------
// GEMM. CTA 128x128, 128 threads (4 warps as 2x2 grid of 64x64 warp tiles).
// SMEM rows 128B, XOR-16B swizzle. 3-stage cp.async pipeline, 2 CTAs/SM,
// register double-buffered ldmatrix fragments. One barrier per chunk; all
// cross-thread SMEM consumption ordered by wait_group -> barrier.
// Boundary order: wait -> sync -> next-chunk LDS -> refill -> ks=3 MMAs.
// ---------------------------------------------------------------------------
__global__ void __launch_bounds__(128, 2) gemm_kernel(float* __restrict__ out) {
    extern __shared__ __align__(1024) char smem[];
    const uint32_t sb = smem_u32(smem);
    const int tid = threadIdx.x;
    const int lid = tid & 31, wid = tid >> 5;
    const int warp_m = wid >> 1, warp_n = wid & 1;      // 2 x 2
    const int m0 = blockIdx.x * TM, n0 = blockIdx.y * TN;

    // ---- cp.async bases: 128 thr = 16 rows x 8 chunks; 8 iters of +16 rows.
    // Swizzle phase (k4 ^ (row&7)) invariant under row += 16.
    const int rbase = tid >> 3, k4 = tid & 7;
    const __half* a_src0 = g_x + (size_t)(m0 + rbase) * KK + k4 * 8;
    const __half* b_src0 = g_w + (size_t)(n0 + rbase) * KK + k4 * 8;
    const uint32_t a_dst0 = sb + rbase * 128 + ((k4 ^ (rbase & 7)) << 4);
    const uint32_t b_dst0 = sb + A_BYTES + rbase * 128 + ((k4 ^ (rbase & 7)) << 4);

    auto issue = [&](int kt) {
        uint32_t so = (uint32_t)(kt % 3) * STAGE_BYTES;
        size_t ko = (size_t)kt * KC;
#pragma unroll
        for (int i = 0; i < 8; i++)                 // A rows rbase+16i
            cp16(a_dst0 + so + i * 2048, a_src0 + ko + (size_t)i * 16 * KK);
#pragma unroll
        for (int i = 0; i < 8; i++)                 // B rows rbase+16i
            cp16(b_dst0 + so + i * 2048, b_src0 + ko + (size_t)i * 16 * KK);
        cp_commit();
    };

    // ---- ldmatrix lane geometry ----
    const int lr = lid & 7;
    const int rowA = warp_m * 64 + lr + ((lid >> 3) & 1) * 8;  // + mi*16
    const int kselA = lid >> 4;                                // + 2*ks
    const int rowB = warp_n * 64 + lr + (lid >> 4) * 8;        // + p*16
    const int kselB = (lid >> 3) & 1;                          // + 2*ks

    uint32_t a[2][4][4], b[2][8][2];
    auto load_frags = [&](uint32_t sA, uint32_t sB, int ks, int buf) {
#pragma unroll
        for (int mi = 0; mi < 4; mi++) {
            uint32_t addr = sA + (uint32_t)(rowA + mi * 16) * 128
                          + ((uint32_t)((2 * ks + kselA) ^ lr) << 4);
            ldsm4(a[buf][mi], addr);
        }
#pragma unroll
        for (int p = 0; p < 4; p++) {
            uint32_t addr = sB + (uint32_t)(rowB + p * 16) * 128
                          + ((uint32_t)((2 * ks + kselB) ^ lr) << 4);
            uint32_t r[4];
            ldsm4(r, addr);
            b[buf][2 * p][0] = r[0];     b[buf][2 * p][1] = r[1];
            b[buf][2 * p + 1][0] = r[2]; b[buf][2 * p + 1][1] = r[3];
        }
    };

    float acc[4][8][4];
#pragma unroll
    for (int mi = 0; mi < 4; mi++)
#pragma unroll
        for (int ni = 0; ni < 8; ni++)
#pragma unroll
            for (int q = 0; q < 4; q++) acc[mi][ni][q] = 0.f;

    // ---- prologue: chunk 0 resident AND visible (wait -> barrier) ----
    issue(0); issue(1); issue(2);
    cp_wait<2>();
    __syncthreads();
    load_frags(sb, sb + A_BYTES, 0, 0);   // (kt=0, ks=0) -> buf 0

#pragma unroll 1
    for (int kt = 0; kt < KTILES; kt++) {
        const uint32_t sA = sb + (uint32_t)(kt % 3) * STAGE_BYTES;
        const uint32_t sB = sA + A_BYTES;
        const uint32_t sAn = sb + (uint32_t)((kt + 1) % 3) * STAGE_BYTES;
        // ks = 0..2: prefetch ks+1 from the (barrier-protected) current chunk
#pragma unroll
        for (int ks = 0; ks < 3; ks++) {
            const int cur = ks & 1, nxt = cur ^ 1;
            load_frags(sA, sB, ks + 1, nxt);
#pragma unroll
            for (int mi = 0; mi < 4; mi++)
#pragma unroll
                for (int ni = 0; ni < 8; ni++)
                    mma16816(acc[mi][ni], a[cur][mi], b[cur][ni]);
        }

        // ---- chunk boundary BEFORE the (register-only) ks=3 MMA block ----
        if (kt + 1 < KTILES) {
            cp_wait<1>();        // own groups: chunk kt+1 landed
            __syncthreads();     // everyone's chunk kt+1 writes visible;
                                 // all smem reads of stage kt%3 already issued
            load_frags(sAn, sAn + A_BYTES, 0, 0);  // dependent LDS first
            issue(kt + 3 < KTILES ? kt + 3 : kt);  // branchless refill after
        }

        // ks = 3: register-only MMAs — hide boundary latency under them
#pragma unroll
        for (int mi = 0; mi < 4; mi++)
#pragma unroll
            for (int ni = 0; ni < 8; ni++)
                mma16816(acc[mi][ni], a[1][mi], b[1][ni]);
    }

    // ---- epilogue: streaming fp32 stores (evict-first; output never re-read)
    const int g = lid >> 2, t = lid & 3;
#pragma unroll
    for (int mi = 0; mi < 4; mi++) {
        int r0 = m0 + warp_m * 64 + mi * 16 + g;
#pragma unroll
        for (int ni = 0; ni < 8; ni++) {
            int c = n0 + warp_n * 64 + ni * 8 + 2 * t;
            stg_cs_v2(out + (size_t)r0 * NN + c,
                      acc[mi][ni][0], acc[mi][ni][1]);
            stg_cs_v2(out + (size_t)(r0 + 8) * NN + c,
                      acc[mi][ni][2], acc[mi][ni][3]);
        }
    }
}

// ---------------------------------------------------------------------------
// Host
// ---------------------------------------------------------------------------
extern "C" void kernel_launch(void* const* d_in, const int* in_sizes, int n_in,
                              void* d_out, int out_size) {
    const float* x = (const float*)d_in[0];
    const int*   w = (const int*)d_in[1];
    const float* sc = (const float*)d_in[2];
    float* out = (float*)d_out;

    cudaFuncSetAttribute(gemm_kernel,
                         cudaFuncAttributeMaxDynamicSharedMemorySize, SMEM_TOTAL);

    prep_kernel<<<XBLOCKS + WBLOCKS, 256>>>(reinterpret_cast<const float4*>(x),
                                            reinterpret_cast<const int4*>(w), sc);
    gemm_kernel<<<dim3(MM / TM, NN / TN), 128, SMEM_TOTAL>>>(out);
}

// round 16
// speedup vs baseline: 1.1391x; 1.0537x over previous
#include <cuda_runtime.h>
#include <cuda_fp16.h>
#include <cstdint>

// ---------------------------------------------------------------------------
// out[8192,11008] = x[8192,4096] @ dequant(W)[11008,4096]^T
// W: int8 stored in int32; scales[11008, 32], group=128 along K.
// fp16 scratch prepass + cp.async/ldmatrix/mma.sync.m16n8k16 GEMM.
// Round 16: R15 with the last in-loop conditional removed. The chunk-
// boundary block (wait/sync/next-LDS/refill) now runs unconditionally;
// at kt=63 it performs a harmless stale read into dead registers and a
// redundant L2-hot refill. Loop body is fully branchless (R10 measured
// ~58us per conditional in this loop).
// ---------------------------------------------------------------------------
#define MM 8192
#define NN 11008
#define KK 4096

#define TM 128
#define TN 128
#define KC 64                              // 64 halves = 128B rows
#define KTILES (KK / KC)                   // 64
#define STAGES 3
#define A_BYTES (TM * KC * 2)              // 16384
#define B_BYTES (TN * KC * 2)              // 16384
#define STAGE_BYTES (A_BYTES + B_BYTES)    // 32768
#define SMEM_TOTAL (STAGES * STAGE_BYTES)  // 98304

#define XBLOCKS 16384                      // prep: x part
#define WBLOCKS 22016                      // prep: w part

__device__ __half g_x[(size_t)MM * KK];    // 67 MB
__device__ __half g_w[(size_t)NN * KK];    // 90 MB

// ---------------------------------------------------------------------------
// PTX helpers (baseline PTX, valid on compute_103)
// ---------------------------------------------------------------------------
__device__ __forceinline__ uint32_t smem_u32(const void* p) {
    uint32_t a;
    asm("{ .reg .u64 t; cvta.to.shared.u64 t, %1; cvt.u32.u64 %0, t; }"
        : "=r"(a) : "l"(p));
    return a;
}

__device__ __forceinline__ void cp16(uint32_t dst, const void* src) {
    asm volatile("cp.async.cg.shared.global [%0], [%1], 16;"
                 :: "r"(dst), "l"(src));
}
__device__ __forceinline__ void cp_commit() {
    asm volatile("cp.async.commit_group;" ::: "memory");
}
template <int N>
__device__ __forceinline__ void cp_wait() {
    asm volatile("cp.async.wait_group %0;" :: "n"(N) : "memory");
}

__device__ __forceinline__ void ldsm4(uint32_t* r, uint32_t addr) {
    asm volatile("ldmatrix.sync.aligned.m8n8.x4.shared.b16 {%0,%1,%2,%3}, [%4];"
                 : "=r"(r[0]), "=r"(r[1]), "=r"(r[2]), "=r"(r[3]) : "r"(addr));
}

__device__ __forceinline__ void mma16816(float* d, const uint32_t* a,
                                         const uint32_t* b) {
    asm volatile(
        "mma.sync.aligned.m16n8k16.row.col.f32.f16.f16.f32 "
        "{%0,%1,%2,%3}, {%4,%5,%6,%7}, {%8,%9}, {%0,%1,%2,%3};"
        : "+f"(d[0]), "+f"(d[1]), "+f"(d[2]), "+f"(d[3])
        : "r"(a[0]), "r"(a[1]), "r"(a[2]), "r"(a[3]), "r"(b[0]), "r"(b[1]));
}

__device__ __forceinline__ void stg_cs_v2(float* p, float v0, float v1) {
    asm volatile("st.global.cs.v2.f32 [%0], {%1, %2};"
                 :: "l"(p), "f"(v0), "f"(v1) : "memory");
}

// ---------------------------------------------------------------------------
// Fused prepass: blocks [0, XBLOCKS) convert x -> g_x (fp16);
// blocks [XBLOCKS, XBLOCKS+WBLOCKS) dequantize W -> g_w (fp16).
// ---------------------------------------------------------------------------
__global__ void __launch_bounds__(256) prep_kernel(const float4* __restrict__ x,
                                                   const int4* __restrict__ w,
                                                   const float* __restrict__ sc) {
    int b = blockIdx.x;
    if (b < XBLOCKS) {
        size_t i = (size_t)b * 256 + threadIdx.x;         // 8-float chunk
        float4 v0 = x[i * 2], v1 = x[i * 2 + 1];
        __half2 h0 = __floats2half2_rn(v0.x, v0.y);
        __half2 h1 = __floats2half2_rn(v0.z, v0.w);
        __half2 h2 = __floats2half2_rn(v1.x, v1.y);
        __half2 h3 = __floats2half2_rn(v1.z, v1.w);
        uint4 o;
        o.x = *reinterpret_cast<uint32_t*>(&h0);
        o.y = *reinterpret_cast<uint32_t*>(&h1);
        o.z = *reinterpret_cast<uint32_t*>(&h2);
        o.w = *reinterpret_cast<uint32_t*>(&h3);
        reinterpret_cast<uint4*>(g_x)[i] = o;
    } else {
        size_t i = (size_t)(b - XBLOCKS) * 256 + threadIdx.x;  // 8-int chunk
        size_t o = i >> 9;
        int c = (int)(i & 511);
        float s = __ldg(&sc[(o << 5) + (c >> 4)]);
        int4 q0 = w[i * 2], q1 = w[i * 2 + 1];
        __half2 h0 = __floats2half2_rn((float)q0.x * s, (float)q0.y * s);
        __half2 h1 = __floats2half2_rn((float)q0.z * s, (float)q0.w * s);
        __half2 h2 = __floats2half2_rn((float)q1.x * s, (float)q1.y * s);
        __half2 h3 = __floats2half2_rn((float)q1.z * s, (float)q1.w * s);
        uint4 ov;
        ov.x = *reinterpret_cast<uint32_t*>(&h0);
        ov.y = *reinterpret_cast<uint32_t*>(&h1);
        ov.z = *reinterpret_cast<uint32_t*>(&h2);
        ov.w = *reinterpret_cast<uint32_t*>(&h3);
        reinterpret_cast<uint4*>(g_w)[i] = ov;
    }
}

// ---------------------------------------------------------------------------
// GEMM. CTA 128x128, 128 threads (4 warps as 2x2 grid of 64x64 warp tiles).
// SMEM rows 128B, XOR-16B swizzle. 3-stage cp.async pipeline, 2 CTAs/SM,
// register double-buffered ldmatrix fragments. One barrier per chunk; all
// cross-thread SMEM consumption ordered by wait_group -> barrier.
// Loop body FULLY branchless: boundary block unconditional (kt=63 does a
// harmless stale read into dead regs + redundant L2-hot refill).
// ---------------------------------------------------------------------------
__global__ void __launch_bounds__(128, 2) gemm_kernel(float* __restrict__ out) {
    extern __shared__ __align__(1024) char smem[];
    const uint32_t sb = smem_u32(smem);
    const int tid = threadIdx.x;
    const int lid = tid & 31, wid = tid >> 5;
    const int warp_m = wid >> 1, warp_n = wid & 1;      // 2 x 2
    const int m0 = blockIdx.x * TM, n0 = blockIdx.y * TN;

    // ---- cp.async bases: 128 thr = 16 rows x 8 chunks; 8 iters of +16 rows.
    // Swizzle phase (k4 ^ (row&7)) invariant under row += 16.
    const int rbase = tid >> 3, k4 = tid & 7;
    const __half* a_src0 = g_x + (size_t)(m0 + rbase) * KK + k4 * 8;
    const __half* b_src0 = g_w + (size_t)(n0 + rbase) * KK + k4 * 8;
    const uint32_t a_dst0 = sb + rbase * 128 + ((k4 ^ (rbase & 7)) << 4);
    const uint32_t b_dst0 = sb + A_BYTES + rbase * 128 + ((k4 ^ (rbase & 7)) << 4);

    auto issue = [&](int kt) {
        uint32_t so = (uint32_t)(kt % 3) * STAGE_BYTES;
        size_t ko = (size_t)kt * KC;
#pragma unroll
        for (int i = 0; i < 8; i++)                 // A rows rbase+16i
            cp16(a_dst0 + so + i * 2048, a_src0 + ko + (size_t)i * 16 * KK);
#pragma unroll
        for (int i = 0; i < 8; i++)                 // B rows rbase+16i
            cp16(b_dst0 + so + i * 2048, b_src0 + ko + (size_t)i * 16 * KK);
        cp_commit();
    };

    // ---- ldmatrix lane geometry ----
    const int lr = lid & 7;
    const int rowA = warp_m * 64 + lr + ((lid >> 3) & 1) * 8;  // + mi*16
    const int kselA = lid >> 4;                                // + 2*ks
    const int rowB = warp_n * 64 + lr + (lid >> 4) * 8;        // + p*16
    const int kselB = (lid >> 3) & 1;                          // + 2*ks

    uint32_t a[2][4][4], b[2][8][2];
    auto load_frags = [&](uint32_t sA, uint32_t sB, int ks, int buf) {
#pragma unroll
        for (int mi = 0; mi < 4; mi++) {
            uint32_t addr = sA + (uint32_t)(rowA + mi * 16) * 128
                          + ((uint32_t)((2 * ks + kselA) ^ lr) << 4);
            ldsm4(a[buf][mi], addr);
        }
#pragma unroll
        for (int p = 0; p < 4; p++) {
            uint32_t addr = sB + (uint32_t)(rowB + p * 16) * 128
                          + ((uint32_t)((2 * ks + kselB) ^ lr) << 4);
            uint32_t r[4];
            ldsm4(r, addr);
            b[buf][2 * p][0] = r[0];     b[buf][2 * p][1] = r[1];
            b[buf][2 * p + 1][0] = r[2]; b[buf][2 * p + 1][1] = r[3];
        }
    };

    float acc[4][8][4];
#pragma unroll
    for (int mi = 0; mi < 4; mi++)
#pragma unroll
        for (int ni = 0; ni < 8; ni++)
#pragma unroll
            for (int q = 0; q < 4; q++) acc[mi][ni][q] = 0.f;

    // ---- prologue: chunk 0 resident AND visible (wait -> barrier) ----
    issue(0); issue(1); issue(2);
    cp_wait<2>();
    __syncthreads();
    load_frags(sb, sb + A_BYTES, 0, 0);   // (kt=0, ks=0) -> buf 0

#pragma unroll 1
    for (int kt = 0; kt < KTILES; kt++) {
        const uint32_t sA = sb + (uint32_t)(kt % 3) * STAGE_BYTES;
        const uint32_t sB = sA + A_BYTES;
        const uint32_t sAn = sb + (uint32_t)((kt + 1) % 3) * STAGE_BYTES;
        // ks = 0..2: prefetch ks+1 from the (barrier-protected) current chunk
#pragma unroll
        for (int ks = 0; ks < 3; ks++) {
            const int cur = ks & 1, nxt = cur ^ 1;
            load_frags(sA, sB, ks + 1, nxt);
#pragma unroll
            for (int mi = 0; mi < 4; mi++)
#pragma unroll
                for (int ni = 0; ni < 8; ni++)
                    mma16816(acc[mi][ni], a[cur][mi], b[cur][ni]);
        }

        // ---- chunk boundary (UNCONDITIONAL; register-only ks=3 follows) ----
        cp_wait<1>();        // own groups: chunk kt+1 landed (kt=63: benign)
        __syncthreads();     // everyone's chunk kt+1 writes visible;
                             // all smem reads of stage kt%3 already issued
        load_frags(sAn, sAn + A_BYTES, 0, 0);  // kt=63: stale read, dead regs
        issue(kt + 3 < KTILES ? kt + 3 : kt);  // branchless refill (select)

        // ks = 3: register-only MMAs — hide boundary latency under them
#pragma unroll
        for (int mi = 0; mi < 4; mi++)
#pragma unroll
            for (int ni = 0; ni < 8; ni++)
                mma16816(acc[mi][ni], a[1][mi], b[1][ni]);
    }

    // ---- epilogue: streaming fp32 stores (evict-first; output never re-read)
    const int g = lid >> 2, t = lid & 3;
#pragma unroll
    for (int mi = 0; mi < 4; mi++) {
        int r0 = m0 + warp_m * 64 + mi * 16 + g;
#pragma unroll
        for (int ni = 0; ni < 8; ni++) {
            int c = n0 + warp_n * 64 + ni * 8 + 2 * t;
            stg_cs_v2(out + (size_t)r0 * NN + c,
                      acc[mi][ni][0], acc[mi][ni][1]);
            stg_cs_v2(out + (size_t)(r0 + 8) * NN + c,
                      acc[mi][ni][2], acc[mi][ni][3]);
        }
    }
}

// ---------------------------------------------------------------------------
// Host
// ---------------------------------------------------------------------------
extern "C" void kernel_launch(void* const* d_in, const int* in_sizes, int n_in,
                              void* d_out, int out_size) {
    const float* x = (const float*)d_in[0];
    const int*   w = (const int*)d_in[1];
    const float* sc = (const float*)d_in[2];
    float* out = (float*)d_out;

    cudaFuncSetAttribute(gemm_kernel,
                         cudaFuncAttributeMaxDynamicSharedMemorySize, SMEM_TOTAL);

    prep_kernel<<<XBLOCKS + WBLOCKS, 256>>>(reinterpret_cast<const float4*>(x),
                                            reinterpret_cast<const int4*>(w), sc);
    gemm_kernel<<<dim3(MM / TM, NN / TN), 128, SMEM_TOTAL>>>(out);
}